// round 16
// baseline (speedup 1.0000x reference)
#include <cuda_runtime.h>
#include <math.h>
#include <stdint.h>

// Problem dims
#define Bb   64
#define Tt   2048
#define INx  64
#define Hh   512
#define OUTD 32
#define K1   576      // INx + Hh
#define NCTA 132      // 4 groups x 33 CTAs
#define GRP  4
#define CPG  33       // lc 0..31: f/z/r cols [16lc,16lc+16); lc=32: y
#define BG   16       // batch rows per group
#define NTHR 512

typedef unsigned long long ull;

// ---- persistent device scratch ----
__device__ float g_x  [Hh * Bb];               // state, transposed [k][m]
__device__ float g_xfT[Hh * Bb];               // f*x, transposed  [k][m]
__device__ float g_uT [(size_t)Tt * INx * Bb]; // u transposed: [t][i][m]
__device__ unsigned g_bar;                     // one-time init barrier
__device__ unsigned g_barF[GRP * 32];          // f-done counters (128B apart)
__device__ unsigned g_barZ[GRP * 32];          // z+y done (x readers done)
__device__ unsigned g_barX[GRP * 32];          // x(t+1) ready

// SMEM layout (floats)
#define OFF_WF  0        // 576*16 = 9216   (y-CTA: wy 512*32=16384 spans WF+WZ)
#define OFF_WZ  9216     // 9216
#define OFF_WR  18432    // 9216
#define OFF_RED 27648    // 8448 (y: 16*528; f/z/r: 16*272; transpose tile 4160)
#define OFF_ZV  36096    // 256
#define OFF_BF  36352    // 16
#define OFF_BZ  36368    // 16
#define OFF_BR  36384    // 16
#define OFF_BY  36400    // 32
#define SMEM_FLOATS 36432
#define SMEM_BYTES  (SMEM_FLOATS * 4)

__device__ __forceinline__ ull bcast2(float v) {
  ull r;
  asm("mov.b64 %0, {%1, %1};" : "=l"(r) : "r"(__float_as_uint(v)));
  return r;
}
__device__ __forceinline__ unsigned poll_at(const unsigned* p) {
  unsigned v;
  asm volatile("ld.acquire.gpu.global.u32 %0, [%1];" : "=r"(v) : "l"(p) : "memory");
  return v;
}
__device__ __forceinline__ void arrive_release(unsigned* p) {
  asm volatile("red.release.gpu.global.add.u32 [%0], %1;" :: "l"(p), "r"(1u) : "memory");
}
__device__ __forceinline__ void unpack2(ull a, float& lo, float& hi) {
  unsigned l, h;
  asm("mov.b64 {%0,%1}, %2;" : "=r"(l), "=r"(h) : "l"(a));
  lo = __uint_as_float(l); hi = __uint_as_float(h);
}
#define FMA2(a, x, w) asm("fma.rn.f32x2 %0, %1, %2, %0;" : "+l"(a) : "l"(x), "l"(w))

// u-segment (4 rows) for a 16-col matmul. acc: [0..1]=m0 colpairs, [2..3]=m1.
__device__ __forceinline__ void useg16(const float* src, const float* wsm, ull acc[4],
                                       int gbase, int m0, int ks, int cs) {
  const float2* up = (const float2*)(src + (ks * 4) * Bb + gbase + m0);
  const float*  wp = wsm + (Hh + ks * 4) * 16 + cs * 4;
  #pragma unroll
  for (int k = 0; k < 4; k++) {
    float2 xv = up[k * (Bb / 2)];
    ull x0b = bcast2(xv.x), x1b = bcast2(xv.y);
    ulonglong2 wA = *(const ulonglong2*)(wp + k * 16);
    FMA2(acc[0], x0b, wA.x); FMA2(acc[1], x0b, wA.y);
    FMA2(acc[2], x1b, wA.x); FMA2(acc[3], x1b, wA.y);
  }
}

// x-segment (32 rows, staged) for a 16-col matmul.
__device__ __forceinline__ void xseg32(const float* src, const float* wsm, ull acc[4],
                                       int gbase, int m0, int ks, int cs) {
  const float2* xp = (const float2*)(src + (ks * 32) * Bb + gbase + m0);
  const float*  wp = wsm + (ks * 32) * 16 + cs * 4;
  float2 buf[8];
  #pragma unroll
  for (int j = 0; j < 8; j++) buf[j] = __ldcg(xp + j * (Bb / 2));
  #pragma unroll
  for (int blk = 0; blk < 4; blk++) {
    float2 nbuf[8];
    if (blk < 3) {
      #pragma unroll
      for (int j = 0; j < 8; j++) nbuf[j] = __ldcg(xp + ((blk + 1) * 8 + j) * (Bb / 2));
    }
    #pragma unroll
    for (int j = 0; j < 8; j++) {
      int k = blk * 8 + j;
      ull x0b = bcast2(buf[j].x), x1b = bcast2(buf[j].y);
      ulonglong2 wA = *(const ulonglong2*)(wp + k * 16);
      FMA2(acc[0], x0b, wA.x); FMA2(acc[1], x0b, wA.y);
      FMA2(acc[2], x1b, wA.x); FMA2(acc[3], x1b, wA.y);
    }
    #pragma unroll
    for (int j = 0; j < 8; j++) buf[j] = nbuf[j];
  }
}

// store 16-col partials: layout [ks][n][BG] (+16 pad per slice)
__device__ __forceinline__ void store16(float* s_red, ull acc[4], int ks, int cs, int m0) {
  float* rp = s_red + ks * 272;
  int colb = cs * 4;
  #pragma unroll
  for (int p = 0; p < 2; p++) {
    float e0, o0, e1, o1;
    unpack2(acc[p],     e0, o0);
    unpack2(acc[2 + p], e1, o1);
    float2 ve; ve.x = e0; ve.y = e1;
    float2 vo; vo.x = o0; vo.y = o1;
    *(float2*)(rp + (colb + 2 * p)     * BG + m0) = ve;
    *(float2*)(rp + (colb + 2 * p + 1) * BG + m0) = vo;
  }
}

__global__ void __launch_bounds__(NTHR, 1) gru_main(
    const float* __restrict__ u,
    const float* __restrict__ x0,
    const float* __restrict__ kernel_fz, const float* __restrict__ bias_fz,
    const float* __restrict__ kernel_r,  const float* __restrict__ bias_r,
    const float* __restrict__ W_out,     const float* __restrict__ b_out,
    float* __restrict__ out)
{
  extern __shared__ float smem[];
  float* s_wf  = smem + OFF_WF;
  float* s_wz  = smem + OFF_WZ;
  float* s_wr  = smem + OFF_WR;
  float* s_red = smem + OFF_RED;
  float* s_zv  = smem + OFF_ZV;
  float* s_bf  = smem + OFF_BF;
  float* s_bz  = smem + OFF_BZ;
  float* s_br  = smem + OFF_BR;
  float* s_by  = smem + OFF_BY;

  const int tid = threadIdx.x;
  const int cid = blockIdx.x;
  const int grp = cid / CPG;
  const int lc  = cid - grp * CPG;     // 0..32
  const int gbase = grp * BG;
  const int mg  = tid & 7;             // m-pair
  const int cs  = (tid >> 3) & 3;      // column split
  const int ks  = tid >> 5;            // K-slice 0..15
  const int m0  = 2 * mg;
  unsigned* barF = &g_barF[grp * 32];
  unsigned* barZ = &g_barZ[grp * 32];
  unsigned* barX = &g_barX[grp * 32];

  // ---- stationary weights ----
  if (lc < 32) {
    for (int i = tid; i < K1 * 16; i += NTHR) {
      int kk = i / 16, n = i % 16;
      int row = (kk < Hh) ? (INx + kk) : (kk - Hh);   // [u | x] concat order
      s_wf[i] = kernel_fz[row * (2 * Hh) + lc * 16 + n];
      s_wz[i] = kernel_fz[row * (2 * Hh) + Hh + lc * 16 + n];
      s_wr[i] = kernel_r[row * Hh + lc * 16 + n];
    }
    if (tid < 16) {
      s_bf[tid] = bias_fz[lc * 16 + tid];
      s_bz[tid] = bias_fz[Hh + lc * 16 + tid];
      s_br[tid] = bias_r[lc * 16 + tid];
    }
  } else {
    // y-CTA: wy [kk][32] occupying WF+WZ region
    for (int i = tid; i < Hh * 32; i += NTHR) {
      int kk = i / 32, n = i % 32;
      smem[OFF_WF + i] = W_out[n * Hh + kk];
    }
    if (tid < OUTD) s_by[tid] = b_out[tid];
  }

  // ---- in-kernel init: x0 -> g_x ----
  for (int idx = cid * NTHR + tid; idx < Hh * Bb; idx += NCTA * NTHR) {
    int k = idx >> 6, mm = idx & 63;
    g_x[idx] = x0[mm * Hh + k];
  }

  // ---- in-kernel u transpose ----
  {
    float* tile = s_red;                 // 4160 floats, fits in RED (8448)
    __syncthreads();
    for (int t = cid; t < Tt; t += NCTA) {
      for (int idx = tid; idx < INx * Bb; idx += NTHR) {
        int mm = idx >> 6, i = idx & 63;
        tile[mm * 65 + i] = u[((size_t)mm * Tt + t) * INx + i];
      }
      __syncthreads();
      for (int idx = tid; idx < INx * Bb; idx += NTHR) {
        g_uT[(size_t)t * (INx * Bb) + idx] = tile[(idx & 63) * 65 + (idx >> 6)];
      }
      __syncthreads();
    }
  }

  // ---- one-time global barrier ----
  __threadfence();
  __syncthreads();
  if (tid == 0) atomicAdd(&g_bar, 1u);
  if (tid == 0) { while (poll_at(&g_bar) < NCTA) { } }
  __syncthreads();

  if (lc < 32) {
    // prefetch f's u-segment for t=0
    ull acc_fu[4] = {0ull, 0ull, 0ull, 0ull};
    useg16(g_uT, s_wf, acc_fu, gbase, m0, ks, cs);

    for (int t = 0; t < Tt; t++) {
      const float* uT_t = g_uT + (size_t)t * (INx * Bb);

      // ===== f matmul (on recurrence path) =====
      {
        ull acc[4] = {acc_fu[0], acc_fu[1], acc_fu[2], acc_fu[3]};
        xseg32(g_x, s_wf, acc, gbase, m0, ks, cs);
        store16(s_red, acc, ks, cs, m0);
        __syncthreads();
        if (tid < 256) {
          int mm = tid & 15, n = tid >> 4;
          float s = s_bf[n];
          #pragma unroll
          for (int q = 0; q < 16; q++) s += s_red[q * 272 + n * BG + mm];
          int c = lc * 16 + n;
          float f = 1.0f / (1.0f + expf(-s));
          g_xfT[c * Bb + gbase + mm] = f * __ldcg(&g_x[c * Bb + gbase + mm]);
        }
        __syncthreads();
        if (tid == 0) arrive_release(barF);
      }

      // ===== z matmul (shadow work: hides F-detect) =====
      {
        ull acc[4] = {0ull, 0ull, 0ull, 0ull};
        useg16(uT_t, s_wz, acc, gbase, m0, ks, cs);
        xseg32(g_x, s_wz, acc, gbase, m0, ks, cs);
        __syncthreads();            // f-epilogue reads of s_red done before overwrite
        store16(s_red, acc, ks, cs, m0);
        __syncthreads();
        if (tid < 256) {
          int mm = tid & 15, n = tid >> 4;
          float s = s_bz[n];
          #pragma unroll
          for (int q = 0; q < 16; q++) s += s_red[q * 272 + n * BG + mm];
          s_zv[n * BG + mm] = 1.0f / (1.0f + expf(-s));
        }
        __syncthreads();
        if (tid == 0) arrive_release(barZ);   // also: my x(t) reads are done
      }

      // ===== r matmul (on recurrence path) =====
      ull acc_r[4] = {0ull, 0ull, 0ull, 0ull};
      useg16(uT_t, s_wr, acc_r, gbase, m0, ks, cs);
      if (tid == 0) { unsigned need = 32u * (t + 1); while (poll_at(barF) < need) { } }
      __syncthreads();
      xseg32(g_xfT, s_wr, acc_r, gbase, m0, ks, cs);
      store16(s_red, acc_r, ks, cs, m0);
      __syncthreads();

      // wait all x(t) readers (z + y) before overwriting x
      if (tid == 0) { unsigned need = 33u * (t + 1); while (poll_at(barZ) < need) { } }
      __syncthreads();
      if (tid < 256) {
        int mm = tid & 15, n = tid >> 4;
        float s = s_br[n];
        #pragma unroll
        for (int q = 0; q < 16; q++) s += s_red[q * 272 + n * BG + mm];
        int j = lc * 16 + n;
        float r  = tanhf(s);
        float z  = s_zv[n * BG + mm];
        float xo = __ldcg(&g_x[j * Bb + gbase + mm]);
        g_x[j * Bb + gbase + mm] = (1.0f - z) * xo + z * r;
      }
      __syncthreads();
      if (tid == 0) arrive_release(barX);

      // prefetch f's u-segment for t+1 while waiting for x(t+1)
      {
        int tn = (t + 1 < Tt) ? (t + 1) : (Tt - 1);
        acc_fu[0] = acc_fu[1] = acc_fu[2] = acc_fu[3] = 0ull;
        useg16(g_uT + (size_t)tn * (INx * Bb), s_wf, acc_fu, gbase, m0, ks, cs);
      }
      if (tid == 0) { unsigned need = 32u * (t + 1); while (poll_at(barX) < need) { } }
      __syncthreads();
    }
  } else {
    // ===== y-CTA: y(t) = x(t) @ W_out^T + b_out (32 cols, K=512) =====
    const float* s_wy = smem + OFF_WF;
    for (int t = 0; t < Tt; t++) {
      ull acc[8];
      #pragma unroll
      for (int p = 0; p < 8; p++) acc[p] = 0ull;
      { // x segment, 32 cols: cs picks 8 cols
        const float2* xp = (const float2*)(g_x + (ks * 32) * Bb + gbase + m0);
        const float*  wp = s_wy + (ks * 32) * 32 + cs * 8;
        float2 buf[8];
        #pragma unroll
        for (int j = 0; j < 8; j++) buf[j] = __ldcg(xp + j * (Bb / 2));
        #pragma unroll
        for (int blk = 0; blk < 4; blk++) {
          float2 nbuf[8];
          if (blk < 3) {
            #pragma unroll
            for (int j = 0; j < 8; j++) nbuf[j] = __ldcg(xp + ((blk + 1) * 8 + j) * (Bb / 2));
          }
          #pragma unroll
          for (int j = 0; j < 8; j++) {
            int k = blk * 8 + j;
            ull x0b = bcast2(buf[j].x), x1b = bcast2(buf[j].y);
            const ulonglong2* wv = (const ulonglong2*)(wp + k * 32);
            ulonglong2 wA = wv[0], wB = wv[1];
            FMA2(acc[0], x0b, wA.x); FMA2(acc[1], x0b, wA.y);
            FMA2(acc[2], x0b, wB.x); FMA2(acc[3], x0b, wB.y);
            FMA2(acc[4], x1b, wA.x); FMA2(acc[5], x1b, wA.y);
            FMA2(acc[6], x1b, wB.x); FMA2(acc[7], x1b, wB.y);
          }
          #pragma unroll
          for (int j = 0; j < 8; j++) buf[j] = nbuf[j];
        }
      }
      { // partials: [ks][n(32)][BG], slice stride 528
        float* rp = s_red + ks * 528;
        int colb = cs * 8;
        #pragma unroll
        for (int p = 0; p < 4; p++) {
          float e0, o0, e1, o1;
          unpack2(acc[p],     e0, o0);
          unpack2(acc[4 + p], e1, o1);
          float2 ve; ve.x = e0; ve.y = e1;
          float2 vo; vo.x = o0; vo.y = o1;
          *(float2*)(rp + (colb + 2 * p)     * BG + m0) = ve;
          *(float2*)(rp + (colb + 2 * p + 1) * BG + m0) = vo;
        }
      }
      __syncthreads();
      { // epilogue: 16 batch x 32 cols over 512 threads
        int mm = tid & 15, n = tid >> 4;
        float s = s_by[n];
        #pragma unroll
        for (int q = 0; q < 16; q++) s += s_red[q * 528 + n * BG + mm];
        out[((size_t)(gbase + mm) * Tt + t) * OUTD + n] = s;
      }
      __syncthreads();
      if (tid == 0) arrive_release(barZ);     // y's x(t) reads done
      if (tid == 0) { unsigned need = 32u * (t + 1); while (poll_at(barX) < need) { } }
      __syncthreads();
    }
  }
}

// Runs BEFORE gru_main: resets counters; keeps gru_main as ncu launch #6.
__global__ void zero_bar_kernel() {
  g_bar = 0u;
  for (int i = 0; i < GRP; i++) {
    g_barF[i * 32] = 0u; g_barZ[i * 32] = 0u; g_barX[i * 32] = 0u;
  }
}

extern "C" void kernel_launch(void* const* d_in, const int* in_sizes, int n_in,
                              void* d_out, int out_size) {
  const float *u = 0, *x0 = 0, *kernel_fz = 0, *bias_fz = 0,
              *kernel_r = 0, *bias_r = 0, *W_out = 0, *b_out = 0;
  for (int i = 0; i < n_in; i++) {
    const float* p = (const float*)d_in[i];
    switch (in_sizes[i]) {
      case 8388608: u         = p; break;
      case 32768:   x0        = p; break;
      case 589824:  kernel_fz = p; break;
      case 1024:    bias_fz   = p; break;
      case 294912:  kernel_r  = p; break;
      case 512:     bias_r    = p; break;
      case 16384:   W_out     = p; break;
      case 32:      b_out     = p; break;
      default: break;
    }
  }
  if (!u || !x0 || !kernel_fz || !bias_fz || !kernel_r || !bias_r || !W_out || !b_out) {
    u         = (const float*)d_in[0];
    x0        = (const float*)d_in[1];
    kernel_fz = (const float*)d_in[2];
    bias_fz   = (const float*)d_in[3];
    kernel_r  = (const float*)d_in[4];
    bias_r    = (const float*)d_in[5];
    W_out     = (const float*)d_in[6];
    b_out     = (const float*)d_in[7];
  }
  float* out = (float*)d_out;

  static int smem_set = 0;
  if (!smem_set) {
    cudaFuncSetAttribute(gru_main, cudaFuncAttributeMaxDynamicSharedMemorySize,
                         SMEM_BYTES);
    smem_set = 1;
  }

  zero_bar_kernel<<<1, 1>>>();

  void* args[] = { (void*)&u, (void*)&x0,
                   (void*)&kernel_fz, (void*)&bias_fz, (void*)&kernel_r,
                   (void*)&bias_r,    (void*)&W_out,   (void*)&b_out,
                   (void*)&out };
  cudaLaunchCooperativeKernel((const void*)gru_main, dim3(NCTA), dim3(NTHR),
                              args, SMEM_BYTES, (cudaStream_t)0);
}